// round 17
// baseline (speedup 1.0000x reference)
#include <cuda_runtime.h>
#include <cuda_fp16.h>
#include <cstdint>

#define HEADS 32
#define D 64
#define S 8192

#define CHUNKS 16
#define CH_S (S / CHUNKS)   // 512
#define SUBS 64
#define B_NIT (CH_S / SUBS) // 8
#define C_ST 128
#define C_TPC 4
#define C_CTAS_PER_HEAD (S / (C_TPC * C_ST))   // 16
#define B_CTAS (CHUNKS * HEADS)                // 512

// ---------------- scratch ----------------
// Zero-initialized at module load; the C role re-zeroes after consumption,
// so every launch (first call and graph replays) sees zeros.
__device__ __align__(16) float g_ctx_acc[HEADS * D * D];    // 512 KB accumulators
__device__ __align__(16) float g_rsum_acc[HEADS * D];
__device__ int g_cnt[HEADS];                                // C arrival counters
__device__ int g_bdone[HEADS];                              // B completion flags

// ---------------- helpers ----------------
__device__ __forceinline__ uint32_t smem_u32(const void* p) {
    uint32_t a;
    asm("{ .reg .u64 t; cvta.to.shared.u64 t, %1; cvt.u32.u64 %0, t; }" : "=r"(a) : "l"(p));
    return a;
}
#define SW(o) ((uint32_t)(o) ^ ((((uint32_t)(o)) >> 3) & 0x70))

__device__ __forceinline__ void ldmx4(uint32_t* r, uint32_t addr) {
    asm volatile("ldmatrix.sync.aligned.m8n8.x4.shared.b16 {%0,%1,%2,%3}, [%4];"
                 : "=r"(r[0]), "=r"(r[1]), "=r"(r[2]), "=r"(r[3]) : "r"(addr));
}
__device__ __forceinline__ void ldmx4t(uint32_t* r, uint32_t addr) {
    asm volatile("ldmatrix.sync.aligned.m8n8.x4.trans.shared.b16 {%0,%1,%2,%3}, [%4];"
                 : "=r"(r[0]), "=r"(r[1]), "=r"(r[2]), "=r"(r[3]) : "r"(addr));
}
__device__ __forceinline__ void mma16816(float* c, const uint32_t* a,
                                         uint32_t b0, uint32_t b1) {
    asm volatile(
        "mma.sync.aligned.m16n8k16.row.col.f32.f16.f16.f32 "
        "{%0,%1,%2,%3}, {%4,%5,%6,%7}, {%8,%9}, {%0,%1,%2,%3};"
        : "+f"(c[0]), "+f"(c[1]), "+f"(c[2]), "+f"(c[3])
        : "r"(a[0]), "r"(a[1]), "r"(a[2]), "r"(a[3]), "r"(b0), "r"(b1));
}
__device__ __forceinline__ uint32_t hf2(float x, float y) {
    uint32_t d;
    asm("cvt.rn.f16x2.f32 %0, %1, %2;" : "=r"(d) : "f"(y), "f"(x));
    return d;
}
__device__ __forceinline__ uint2 pack4(float a, float b, float c, float d) {
    uint2 r;
    r.x = hf2(a, b);
    r.y = hf2(c, d);
    return r;
}

// =====================================================================
// Fused kernel: bids [0, 512) = B role; [512, 1024) = C role.
// B: per (head, chunk=512s): acc[i][j] += sum_s eK[i,s] V[j,s], then
//    releases g_bdone[h].
// C: transforms Q tile 0 BEFORE waiting on g_bdone[h]==16 (overlaps B),
//    then normalizes ctx into smem, self-cleans, and runs the proven
//    R8 mainloop for 4 s-tiles.
// smem (max of roles): 33024 B.
// =====================================================================
#define B_SRS 32768
#define C_EQ 8192
#define C_CS 24576
#define C_SINV 26624
__global__ void __launch_bounds__(256, 4) kernelBC(const float* __restrict__ K,
                                                   const float* __restrict__ V,
                                                   const float* __restrict__ Q,
                                                   float* __restrict__ O) {
    extern __shared__ __align__(1024) char sm[];
    __shared__ int zflag;
    const uint32_t sb = smem_u32(sm);
    const int tid = threadIdx.x, lane = tid & 31, wid = tid >> 5;
    const int bid = blockIdx.x;

    if (bid < B_CTAS) {
        // ================= B role =================
        const int ch = bid & 15, h = bid >> 4;
        float* sRS = (float*)(sm + B_SRS);
        if (tid < 64) sRS[tid] = 0.f;

        const size_t gbase = (size_t)h * D * S + (size_t)ch * CH_S;
        const int wm = wid & 3, wn = wid >> 2;
        const int lr = (lane & 7) + ((lane >> 3) & 1) * 8;
        const int lcs = lane >> 4;

        const int r0 = tid >> 4;
        const int c4 = tid & 15;
        const float* kbase = K + gbase + (size_t)r0 * S + c4 * 4;
        const float* vbase = V + gbase + (size_t)r0 * S + c4 * 4;

        float rs[4] = {0.f, 0.f, 0.f, 0.f};

        auto transform = [&](int t, uint32_t bb) {
            const int off = t * SUBS;
            float4 kv[4], vv[4];
            #pragma unroll
            for (int u = 0; u < 4; u++) {
                kv[u] = *(const float4*)(kbase + (size_t)(16 * u) * S + off);
                vv[u] = *(const float4*)(vbase + (size_t)(16 * u) * S + off);
            }
            #pragma unroll
            for (int u = 0; u < 4; u++) {
                const uint32_t so = SW((r0 + 16 * u) * 128 + c4 * 8);
                float e0 = __expf(kv[u].x), e1 = __expf(kv[u].y);
                float e2 = __expf(kv[u].z), e3 = __expf(kv[u].w);
                rs[u] += (e0 + e1) + (e2 + e3);
                *(uint2*)(sm + bb + so) = pack4(e0, e1, e2, e3);
                *(uint2*)(sm + bb + 8192 + so) = pack4(vv[u].x, vv[u].y, vv[u].z, vv[u].w);
            }
        };

        __syncthreads();
        transform(0, 0);

        float acc[4][4] = {};

        for (int t = 0; t < B_NIT; t++) {
            __syncthreads();
            const uint32_t bb = (uint32_t)(t & 1) * 16384;
            #pragma unroll
            for (int ks = 0; ks < 4; ks++) {
                const uint32_t aoff = SW((16 * wm + lr) * 128 + ks * 32 + lcs * 16);
                uint32_t ah[4];
                ldmx4(ah, sb + bb + aoff);
                uint32_t bh[2][4];
                #pragma unroll
                for (int hlf = 0; hlf < 2; hlf++) {
                    const uint32_t boff =
                        SW((32 * wn + 16 * hlf + lr) * 128 + ks * 32 + lcs * 16);
                    ldmx4(bh[hlf], sb + bb + 8192 + boff);
                }
                #pragma unroll
                for (int nt = 0; nt < 4; nt++) {
                    const int hf = nt >> 1, sub = nt & 1;
                    mma16816(acc[nt], ah, bh[hf][sub], bh[hf][sub + 2]);
                }
            }
            if (t + 1 < B_NIT) transform(t + 1, (uint32_t)((t + 1) & 1) * 16384);
        }

        #pragma unroll
        for (int u = 0; u < 4; u++) {
            float v = rs[u];
            v += __shfl_xor_sync(~0u, v, 1);
            v += __shfl_xor_sync(~0u, v, 2);
            v += __shfl_xor_sync(~0u, v, 4);
            v += __shfl_xor_sync(~0u, v, 8);
            if ((lane & 15) == 0) atomicAdd(&sRS[r0 + 16 * u], v);
        }
        __syncthreads();

        if (tid < 64) atomicAdd(&g_rsum_acc[h * D + tid], sRS[tid]);

        float* pc = g_ctx_acc + (size_t)h * (D * D);
        const int g8 = lane >> 2, tig = lane & 3;
        #pragma unroll
        for (int nt = 0; nt < 4; nt++) {
            const int j = 32 * wn + 8 * nt + 2 * tig;
            const int i0 = 16 * wm + g8;
            atomicAdd(&pc[i0 * D + j], acc[nt][0]);
            atomicAdd(&pc[i0 * D + j + 1], acc[nt][1]);
            atomicAdd(&pc[(i0 + 8) * D + j], acc[nt][2]);
            atomicAdd(&pc[(i0 + 8) * D + j + 1], acc[nt][3]);
        }

        // release: all data atomics fenced, then bump completion flag
        __threadfence();
        __syncthreads();
        if (tid == 0) atomicAdd(&g_bdone[h], 1);

    } else {
        // ================= C role =================
        const int idx = bid - B_CTAS;
        const int stp = idx & 15, h = idx >> 4;
        float* sinv = (float*)(sm + C_SINV);

        if (tid < 128)
            ((float4*)(sm + C_CS))[tid] = make_float4(0.f, 0.f, 0.f, 0.f);
        __syncthreads();        // csum zero visible

        const int s4 = tid & 31, iw = tid >> 5;
        const int tsel = s4 >> 4;
        const int srel = (s4 & 15) * 4;
        const float* qt = Q + (size_t)h * D * S + (size_t)stp * (C_TPC * C_ST)
                        + (size_t)iw * S + s4 * 4;

        auto transform = [&](int t) {
            float* csum = (float*)(sm + C_CS) + t * 128;
            float cs0 = 0.f, cs1 = 0.f, cs2 = 0.f, cs3 = 0.f;
            const float* qb = qt + t * C_ST;
            #pragma unroll
            for (int u = 0; u < 8; u++) {
                float4 qv = *(const float4*)(qb + (size_t)(8 * u) * S);
                float e0 = __expf(qv.x), e1 = __expf(qv.y);
                float e2 = __expf(qv.z), e3 = __expf(qv.w);
                cs0 += e0; cs1 += e1; cs2 += e2; cs3 += e3;
                const int i = iw + 8 * u;
                *(uint2*)(sm + C_EQ + tsel * 8192 + SW(i * 128 + srel * 2)) =
                    pack4(e0, e1, e2, e3);
            }
            atomicAdd(&csum[s4 * 4 + 0], cs0);
            atomicAdd(&csum[s4 * 4 + 1], cs1);
            atomicAdd(&csum[s4 * 4 + 2], cs2);
            atomicAdd(&csum[s4 * 4 + 3], cs3);
        };

        // ---- tile-0 transform BEFORE the wait (overlaps B) ----
        transform(0);

        // ---- wait for this head's B CTAs ----
        if (tid == 0) {
            volatile int* f = &g_bdone[h];
            while (*f != CHUNKS) __nanosleep(200);
        }
        __syncthreads();
        __threadfence();        // acquire: B's atomics now visible

        if (tid < 64) sinv[tid] = 0.125f / g_rsum_acc[h * D + tid];
        __syncthreads();        // sinv visible

        // normalize ctx_acc -> fp16 ctx^T smem tile (swizzled)
        {
            const int j40 = (tid & 15) * 4;
            const int ib = tid >> 4;
            #pragma unroll
            for (int k = 0; k < 4; k++) {
                const int i = ib + 16 * k;
                float4 v = *(const float4*)(g_ctx_acc + (size_t)h * (D * D) + i * D + j40);
                const float s = sinv[i];
                *(__half*)(sm + SW((j40 + 0) * 128 + i * 2)) = __float2half_rn(v.x * s);
                *(__half*)(sm + SW((j40 + 1) * 128 + i * 2)) = __float2half_rn(v.y * s);
                *(__half*)(sm + SW((j40 + 2) * 128 + i * 2)) = __float2half_rn(v.z * s);
                *(__half*)(sm + SW((j40 + 3) * 128 + i * 2)) = __float2half_rn(v.w * s);
            }
        }
        __syncthreads();        // ctx tile ready; this CTA's accumulator reads done

        // ---- self-cleaning: last C CTA of this head zeroes accumulators ----
        if (tid == 0) {
            const int old = atomicAdd(&g_cnt[h], 1);
            zflag = (old == C_CTAS_PER_HEAD - 1);
        }
        __syncthreads();
        if (zflag) {
            float4* pz = (float4*)(g_ctx_acc + (size_t)h * (D * D));
            #pragma unroll
            for (int u = 0; u < D * D / 4 / 256; u++)
                pz[tid + u * 256] = make_float4(0.f, 0.f, 0.f, 0.f);
            if (tid < D / 4)
                ((float4*)(g_rsum_acc + h * D))[tid] = make_float4(0.f, 0.f, 0.f, 0.f);
            if (tid == 0) { g_cnt[h] = 0; g_bdone[h] = 0; }
        }

        const int wm = wid & 3, wn = wid >> 2;
        const int lr = (lane & 7) + ((lane >> 3) & 1) * 8;
        const int lcs = lane >> 4;
        const int g8 = lane >> 2, tig = lane & 3;

        for (int t = 0; t < C_TPC; t++) {
            if (t > 0) {
                transform(t);
                __syncthreads();    // EQ + csum ready
            }

            // ---- MMA (R8 layout: warp = 16 j x 64 s) ----
            float acc[8][4] = {};
            #pragma unroll
            for (int ks = 0; ks < 4; ks++) {
                const uint32_t aoff = SW((16 * wm + lr) * 128 + ks * 32 + lcs * 16);
                uint32_t ah[4];
                ldmx4(ah, sb + aoff);
                #pragma unroll
                for (int nb = 0; nb < 4; nb++) {
                    const uint32_t boff =
                        SW((ks * 16 + lr) * 128 + (nb * 16 + lcs * 8) * 2);
                    uint32_t bh[4];
                    ldmx4t(bh, sb + C_EQ + wn * 8192 + boff);
                    mma16816(acc[2 * nb], ah, bh[0], bh[1]);
                    mma16816(acc[2 * nb + 1], ah, bh[2], bh[3]);
                }
            }

            // ---- epilogue ----
            const float* csum = (float*)(sm + C_CS) + t * 128;
            #pragma unroll
            for (int nt = 0; nt < 8; nt++) {
                const int sl = wn * 64 + nt * 8 + 2 * tig;
                const float2 cs = *(const float2*)&csum[sl];
                const float ix = __frcp_rn(cs.x), iy = __frcp_rn(cs.y);
                const int j = 16 * wm + g8;
                const size_t ob = ((size_t)h * D + j) * S
                                + (size_t)stp * (C_TPC * C_ST) + (size_t)t * C_ST + sl;
                float2 v0 = {acc[nt][0] * ix, acc[nt][1] * iy};
                float2 v1 = {acc[nt][2] * ix, acc[nt][3] * iy};
                *(float2*)(O + ob) = v0;
                *(float2*)(O + ob + 8 * S) = v1;
            }
            __syncthreads();        // MMA/epilogue done before EQ overwrite
        }
    }
}

// =====================================================================
extern "C" void kernel_launch(void* const* d_in, const int* in_sizes, int n_in,
                              void* d_out, int out_size) {
    const float* q = (const float*)d_in[0];
    const float* k = (const float*)d_in[1];
    const float* v = (const float*)d_in[2];
    float* o = (float*)d_out;

    const int smemBC = B_SRS + 256;       // 33024 (covers both roles)
    cudaFuncSetAttribute(kernelBC, cudaFuncAttributeMaxDynamicSharedMemorySize, smemBC);

    kernelBC<<<B_CTAS + C_CTAS_PER_HEAD * HEADS, 256, smemBC>>>(k, v, q, o);
}